// round 9
// baseline (speedup 1.0000x reference)
#include <cuda_runtime.h>

// ---------------- problem constants ----------------
#define B_SZ     256
#define NCAPS    1152
#define NCLS     10
#define NROWS    9216        // 1152*8 = 256*36
#define CI_ROWS  160         // 10*16

// ---------------- device scratch (no allocs allowed) ----------------
__device__ float g_h1[(long)B_SZ * 256 * 400];             // 105 MB   conv1 out [b][ci][20*20]
__device__ float g_w2t[(long)256 * 256 * 81];              // 21 MB    [ci][co][81]
__device__ float g_X[(long)NROWS * B_SZ];                  // 9.4 MB   [co*36+p][b]
__device__ float g_uhat[(long)NCLS * NCAPS * 16 * B_SZ];   // 189 MB   [c][n][i][b]
__device__ float g_blog[CI_ROWS * NCAPS];                  // [ (c,i) ][n]
__device__ float g_probs[CI_ROWS * NCAPS];                 // [ (c,i) ][n]
__device__ float g_outputs[CI_ROWS * B_SZ];                // [ (c,i) ][b]

// ---------------- packed f32x2 helpers (Blackwell FFMA2 path) ----------------
#define PACK2(out, lo, hi) \
    asm("mov.b64 %0, {%1, %2};" : "=l"(out) : "f"(lo), "f"(hi))
#define UNPACK2(lo, hi, in) \
    asm("mov.b64 {%0, %1}, %2;" : "=f"(lo), "=f"(hi) : "l"(in))
#define FMA2(acc, a, b) \
    asm("fma.rn.f32x2 %0, %1, %2, %0;" : "+l"(acc) : "l"(a), "l"(b))

// ---------------- repack conv2 weights: [co][ci][81] -> [ci][co][81] ----------------
__global__ void repack_w2(const float* __restrict__ w2) {
    int idx = blockIdx.x * 256 + threadIdx.x;              // 5,308,416 total (exact)
    int k  = idx % 81;
    int co = (idx / 81) % 256;
    int ci = idx / 20736;
    g_w2t[idx] = w2[(co * 256 + ci) * 81 + k];
}

// ---------------- conv1 + bias + relu ----------------
// grid (8 cog, 256 b), 256 threads. smem: 28x28 image + 32 channels of 9x9 weights.
__global__ void conv1_kernel(const float* __restrict__ x,
                             const float* __restrict__ w1,
                             const float* __restrict__ b1) {
    __shared__ float img[784];
    __shared__ float wts[32 * 81];
    int cog = blockIdx.x, b = blockIdx.y;
    const float4* xs = (const float4*)(x + b * 784);
    for (int i = threadIdx.x; i < 196; i += 256) ((float4*)img)[i] = xs[i];
    const float4* ws = (const float4*)(w1 + cog * 2592);
    for (int i = threadIdx.x; i < 648; i += 256) ((float4*)wts)[i] = ws[i];
    __syncthreads();

    // 32 co * 20 oy * 5 quads = 3200 jobs, 1x4 micro-tile in x
    for (int job = threadIdx.x; job < 3200; job += 256) {
        int co_l = job / 100;
        int rem  = job % 100;
        int oy   = rem / 5;
        int qx   = (rem % 5) * 4;
        float a0 = 0.f, a1 = 0.f, a2 = 0.f, a3 = 0.f;
        const float* wr = wts + co_l * 81;
        #pragma unroll
        for (int ky = 0; ky < 9; ++ky) {
            const float* ir = img + (oy + ky) * 28 + qx;
            float in[12];
            #pragma unroll
            for (int t = 0; t < 12; ++t) in[t] = ir[t];
            #pragma unroll
            for (int kx = 0; kx < 9; ++kx) {
                float w = wr[ky * 9 + kx];
                a0 += w * in[kx + 0];
                a1 += w * in[kx + 1];
                a2 += w * in[kx + 2];
                a3 += w * in[kx + 3];
            }
        }
        int co = cog * 32 + co_l;
        float bias = b1[co];
        float4 o;
        o.x = fmaxf(a0 + bias, 0.f);
        o.y = fmaxf(a1 + bias, 0.f);
        o.z = fmaxf(a2 + bias, 0.f);
        o.w = fmaxf(a3 + bias, 0.f);
        *(float4*)(g_h1 + (long)(b * 256 + co) * 400 + oy * 20 + qx) = o;
    }
}

// ---------------- conv2 as implicit GEMM, packed f32x2 accumulation ----------------
// C[co, bp] = sum_{ci,ky,kx} w2[co,ci,ky,kx] * h1[b,ci,2py+ky,2px+kx] + bias
// grid (144 col-tiles of 64, 2 row-tiles of 128), 128 threads (16x8), 8x8 micro-tile.
// Accumulators are column-paired f32x2: numerics identical to scalar version.
__global__ void __launch_bounds__(128, 2) conv2_kernel(const float* __restrict__ b2) {
    __shared__ float a_s[128 * 81];       // 41472 B
    __shared__ float imgs[3 * 400];       // 4800 B
    __shared__ int   cbase_s[64];
    __shared__ int   pp_s[64];
    __shared__ int   bb_s[64];

    int ct = blockIdx.x;                  // 0..143
    int mt = blockIdx.y;                  // 0..1
    int tid = threadIdx.x;                // 0..127
    int col0 = ct * 64;
    int b0 = col0 / 36;
    int nB = (col0 + 63) / 36 - b0 + 1;   // <= 3

    if (tid < 64) {
        int bp = col0 + tid;
        int bidx = bp / 36, p = bp % 36;
        cbase_s[tid] = (bidx - b0) * 400 + (p / 6) * 40 + (p % 6) * 2;
        pp_s[tid] = p;
        bb_s[tid] = bidx;
    }
    __syncthreads();

    int ty = tid / 8, tx = tid % 8;       // rows: ty*8..+7 ; cols: tx*8..+7
    int cb[8];
    #pragma unroll
    for (int cc = 0; cc < 8; ++cc) cb[cc] = cbase_s[tx * 8 + cc];

    unsigned long long acc2[8][4];
    #pragma unroll
    for (int r = 0; r < 8; ++r)
        #pragma unroll
        for (int cp = 0; cp < 4; ++cp) acc2[r][cp] = 0ull;   // (0.f, 0.f)

    int arow = ty * 8 * 81;

    for (int ci = 0; ci < 256; ++ci) {
        __syncthreads();
        // A tile: w2t[ci][mt*128 .. +127][81] -- contiguous 10368 floats
        const float4* asrc = (const float4*)(g_w2t + (long)ci * 20736 + mt * 10368);
        for (int i = tid; i < 2592; i += 128) ((float4*)a_s)[i] = asrc[i];
        // images for the <=3 batches this tile covers
        for (int i = tid; i < nB * 100; i += 128) {
            int nb = i / 100, v = i % 100;
            ((float4*)imgs)[nb * 100 + v] =
                ((const float4*)(g_h1 + (long)((b0 + nb) * 256 + ci) * 400))[v];
        }
        __syncthreads();

        #pragma unroll 1
        for (int ky = 0; ky < 9; ++ky) {
            #pragma unroll
            for (int kx = 0; kx < 9; ++kx) {
                int k    = ky * 9 + kx;
                int koff = ky * 20 + kx;
                unsigned long long bvp[4];
                #pragma unroll
                for (int cp = 0; cp < 4; ++cp) {
                    float blo = imgs[cb[2 * cp]     + koff];
                    float bhi = imgs[cb[2 * cp + 1] + koff];
                    PACK2(bvp[cp], blo, bhi);
                }
                #pragma unroll
                for (int rr = 0; rr < 8; ++rr) {
                    float av = a_s[arow + rr * 81 + k];
                    unsigned long long avp;
                    PACK2(avp, av, av);
                    #pragma unroll
                    for (int cp = 0; cp < 4; ++cp) FMA2(acc2[rr][cp], avp, bvp[cp]);
                }
            }
        }
    }

    #pragma unroll
    for (int rr = 0; rr < 8; ++rr) {
        int co = mt * 128 + ty * 8 + rr;
        float bias = b2[co];
        #pragma unroll
        for (int cp = 0; cp < 4; ++cp) {
            float vlo, vhi;
            UNPACK2(vlo, vhi, acc2[rr][cp]);
            int c0 = tx * 8 + 2 * cp;
            g_X[(long)(co * 36 + pp_s[c0]) * 256 + bb_s[c0]]         = vlo + bias;
            g_X[(long)(co * 36 + pp_s[c0 + 1]) * 256 + bb_s[c0 + 1]] = vhi + bias;
        }
    }
}

// ---------------- primary squash: scale = sq/(1+sq), per (b, n) over 8 dims ----------------
__global__ void squash_primary_kernel() {
    int n = blockIdx.x;       // 1152
    int b = threadIdx.x;      // 256
    float v[8];
    float sq = 0.f;
    #pragma unroll
    for (int j = 0; j < 8; ++j) {
        v[j] = g_X[(long)(n * 8 + j) * 256 + b];
        sq += v[j] * v[j];
    }
    float sc = sq / (1.f + sq);
    #pragma unroll
    for (int j = 0; j < 8; ++j) g_X[(long)(n * 8 + j) * 256 + b] = v[j] * sc;
}

// ---------------- u_hat[c][n][i][b] = sum_j W[c,n,i,j] * X[n*8+j][b] ----------------
__global__ void uhat_kernel(const float* __restrict__ W) {
    int cn = blockIdx.x;      // 0..11519
    int n = cn % 1152;
    int b = threadIdx.x;
    __shared__ float w_s[128];
    if (threadIdx.x < 128) w_s[threadIdx.x] = W[(long)cn * 128 + threadIdx.x];
    __syncthreads();
    float xv[8];
    #pragma unroll
    for (int j = 0; j < 8; ++j) xv[j] = g_X[(long)(n * 8 + j) * 256 + b];
    #pragma unroll
    for (int i = 0; i < 16; ++i) {
        float a = 0.f;
        #pragma unroll
        for (int j = 0; j < 8; ++j) a += w_s[i * 8 + j] * xv[j];
        g_uhat[((long)cn * 16 + i) * 256 + b] = a;
    }
}

__global__ void zero_blog() {
    int i = blockIdx.x * 256 + threadIdx.x;
    if (i < CI_ROWS * NCAPS) g_blog[i] = 0.f;
}

// ---------------- routing: softmax over n per (c,i) ----------------
__global__ void probs_kernel() {
    int ci = blockIdx.x;      // 160
    const float* row = g_blog + ci * 1152;
    __shared__ float red[256];
    int t = threadIdx.x;
    float m = -1e30f;
    for (int n = t; n < 1152; n += 256) m = fmaxf(m, row[n]);
    red[t] = m; __syncthreads();
    for (int s = 128; s > 0; s >>= 1) { if (t < s) red[t] = fmaxf(red[t], red[t + s]); __syncthreads(); }
    float mx = red[0]; __syncthreads();
    float sum = 0.f;
    for (int n = t; n < 1152; n += 256) sum += expf(row[n] - mx);
    red[t] = sum; __syncthreads();
    for (int s = 128; s > 0; s >>= 1) { if (t < s) red[t] += red[t + s]; __syncthreads(); }
    float tot = red[0];
    for (int n = t; n < 1152; n += 256) g_probs[ci * 1152 + n] = expf(row[n] - mx) / tot;
}

// ---------------- s = sum_n probs * u_hat, then squash over batch ----------------
// uniform != 0: first iteration, probs are exactly 1/1152 (logits all zero).
__global__ void s_squash_kernel(int uniform) {
    int ci = blockIdx.x;      // 160
    int c = ci >> 4, i = ci & 15;
    int b = threadIdx.x;
    __shared__ float p_s[1152];
    if (!uniform) {
        for (int n = threadIdx.x; n < 1152; n += 256) p_s[n] = g_probs[ci * 1152 + n];
        __syncthreads();
    }
    const float* uh = g_uhat + ((long)(c * 1152) * 16 + i) * 256 + b;
    float acc = 0.f;
    if (uniform) {
        #pragma unroll 8
        for (int n = 0; n < 1152; ++n) acc += uh[(long)n * 4096];
        acc *= (1.0f / 1152.0f);
    } else {
        #pragma unroll 8
        for (int n = 0; n < 1152; ++n) acc += p_s[n] * uh[(long)n * 4096];
    }
    __shared__ float red[256];
    red[b] = acc * acc; __syncthreads();
    for (int s = 128; s > 0; s >>= 1) { if (b < s) red[b] += red[b + s]; __syncthreads(); }
    float sq = red[0];
    float sc = sq / ((1.f + sq) * sqrtf(sq));
    g_outputs[ci * 256 + b] = acc * sc;
}

// ---------------- delta_b[c,i,n] += sum_b u_hat[c,n,i,b] * outputs[ci,b] ----------------
__global__ void delta_kernel() {
    int ci = blockIdx.x;      // grid (160, 8)
    int chunk = blockIdx.y;
    int c = ci >> 4, i = ci & 15;
    int t = threadIdx.x, w = t >> 5, lane = t & 31;
    __shared__ float out_s[256];
    out_s[t] = g_outputs[ci * 256 + t];
    __syncthreads();
    const float* uh = g_uhat + ((long)(c * 1152) * 16 + i) * 256;
    for (int nn = 0; nn < 18; ++nn) {
        int n = chunk * 144 + w * 18 + nn;
        const float* up = uh + (long)n * 4096;
        float v = 0.f;
        #pragma unroll
        for (int k = 0; k < 8; ++k) { int bb = lane + 32 * k; v += up[bb] * out_s[bb]; }
        #pragma unroll
        for (int o = 16; o > 0; o >>= 1) v += __shfl_down_sync(0xffffffffu, v, o);
        if (lane == 0) g_blog[ci * 1152 + n] += v;
    }
}

// ---------------- final: out[b][c] = sum_i outputs[(c,i)][b]^2 ----------------
__global__ void final_kernel(float* __restrict__ out) {
    int cblk = blockIdx.x;    // 10
    int b = threadIdx.x;      // 256
    float s = 0.f;
    #pragma unroll
    for (int i = 0; i < 16; ++i) {
        float v = g_outputs[(cblk * 16 + i) * 256 + b];
        s += v * v;
    }
    out[b * 10 + cblk] = s;
}

// ---------------- launch ----------------
extern "C" void kernel_launch(void* const* d_in, const int* in_sizes, int n_in,
                              void* d_out, int out_size) {
    const float* x  = (const float*)d_in[0];
    const float* w1 = (const float*)d_in[1];
    const float* b1 = (const float*)d_in[2];
    const float* w2 = (const float*)d_in[3];
    const float* b2 = (const float*)d_in[4];
    const float* W  = (const float*)d_in[5];

    repack_w2<<<20736, 256>>>(w2);
    conv1_kernel<<<dim3(8, 256), 256>>>(x, w1, b1);
    conv2_kernel<<<dim3(144, 2), 128>>>(b2);
    squash_primary_kernel<<<1152, 256>>>();
    uhat_kernel<<<11520, 256>>>(W);
    zero_blog<<<720, 256>>>();
    for (int it = 0; it < 3; ++it) {
        if (it > 0) probs_kernel<<<160, 256>>>();
        s_squash_kernel<<<160, 256>>>(it == 0 ? 1 : 0);
        if (it < 2) delta_kernel<<<dim3(160, 8), 256>>>();
    }
    final_kernel<<<10, 256>>>((float*)d_out);
}

// round 16
// speedup vs baseline: 1.4115x; 1.4115x over previous
#include <cuda_runtime.h>
#include <cuda_bf16.h>

// ---------------- problem constants ----------------
#define B_SZ     256
#define NCAPS    1152
#define NCLS     10
#define NROWS    9216        // 1152*8 = 256*36
#define CI_ROWS  160         // 10*16

// ---------------- device scratch (no allocs allowed) ----------------
__device__ float g_h1[(long)B_SZ * 256 * 400];             // 105 MB   conv1 out [b][ci][20*20]
__device__ uint4 g_w2f[3145728];                           // 50 MB    prepacked A fragments (bf16 hi/lo)
__device__ float g_X[(long)NROWS * B_SZ];                  // 9.4 MB   [co*36+p][b]
__device__ float g_uhat[(long)NCLS * NCAPS * 16 * B_SZ];   // 189 MB   [c][n][i][b]
__device__ float g_blog[CI_ROWS * NCAPS];                  // [ (c,i) ][n]
__device__ float g_probs[CI_ROWS * NCAPS];                 // [ (c,i) ][n]
__device__ float g_outputs[CI_ROWS * B_SZ];                // [ (c,i) ][b]

// ---------------- bf16 mma helper ----------------
#define MMA_BF16(Cr, Af, b0_, b1_) \
    asm volatile("mma.sync.aligned.m16n8k16.row.col.f32.bf16.bf16.f32 " \
        "{%0,%1,%2,%3}, {%4,%5,%6,%7}, {%8,%9}, {%0,%1,%2,%3};" \
        : "+f"(Cr[0]), "+f"(Cr[1]), "+f"(Cr[2]), "+f"(Cr[3]) \
        : "r"(Af.x), "r"(Af.y), "r"(Af.z), "r"(Af.w), "r"(b0_), "r"(b1_))

// ---------------- prepack conv2 weights into A-fragment layout ----------------
// w2 [co][ci][81] fp32 -> g_w2f[((((ci*2+mt)*6+c)*8+mg)*2+s)*32+lane] = uint4{a0,a1,a2,a3}
// s=0: bf16(hi), s=1: bf16(v - hi). k padded 81->96 with zeros.
__global__ void prepack_w2(const float* __restrict__ w2) {
    int idx = blockIdx.x * 256 + threadIdx.x;   // 3,145,728 exact
    int lane = idx & 31;
    int tmp = idx >> 5;
    int s  = tmp & 1;  tmp >>= 1;
    int mg = tmp & 7;  tmp >>= 3;
    int c  = tmp % 6;  tmp /= 6;
    int mt = tmp & 1;
    int ci = tmp >> 1;
    int gg = lane >> 2, tt = lane & 3;
    int co0 = mt * 128 + mg * 16 + gg;
    int k0  = c * 16 + 2 * tt;
    int co_arr[4] = {co0, co0 + 8, co0, co0 + 8};
    int k_arr[4]  = {k0,  k0,     k0 + 8, k0 + 8};
    unsigned out[4];
    #pragma unroll
    for (int j = 0; j < 4; ++j) {
        unsigned bits[2];
        #pragma unroll
        for (int e = 0; e < 2; ++e) {
            int k = k_arr[j] + e;
            float v = (k < 81) ? w2[((long)co_arr[j] * 256 + ci) * 81 + k] : 0.f;
            __nv_bfloat16 bh = __float2bfloat16(v);
            if (s == 0) {
                bits[e] = (unsigned)__bfloat16_as_ushort(bh);
            } else {
                float r = v - __bfloat162float(bh);
                bits[e] = (unsigned)__bfloat16_as_ushort(__float2bfloat16(r));
            }
        }
        out[j] = bits[0] | (bits[1] << 16);
    }
    g_w2f[idx] = make_uint4(out[0], out[1], out[2], out[3]);
}

// ---------------- conv1 + bias + relu (unchanged, verified) ----------------
__global__ void conv1_kernel(const float* __restrict__ x,
                             const float* __restrict__ w1,
                             const float* __restrict__ b1) {
    __shared__ float img[784];
    __shared__ float wts[32 * 81];
    int cog = blockIdx.x, b = blockIdx.y;
    const float4* xs = (const float4*)(x + b * 784);
    for (int i = threadIdx.x; i < 196; i += 256) ((float4*)img)[i] = xs[i];
    const float4* ws = (const float4*)(w1 + cog * 2592);
    for (int i = threadIdx.x; i < 648; i += 256) ((float4*)wts)[i] = ws[i];
    __syncthreads();

    for (int job = threadIdx.x; job < 3200; job += 256) {
        int co_l = job / 100;
        int rem  = job % 100;
        int oy   = rem / 5;
        int qx   = (rem % 5) * 4;
        float a0 = 0.f, a1 = 0.f, a2 = 0.f, a3 = 0.f;
        const float* wr = wts + co_l * 81;
        #pragma unroll
        for (int ky = 0; ky < 9; ++ky) {
            const float* ir = img + (oy + ky) * 28 + qx;
            float in[12];
            #pragma unroll
            for (int t = 0; t < 12; ++t) in[t] = ir[t];
            #pragma unroll
            for (int kx = 0; kx < 9; ++kx) {
                float w = wr[ky * 9 + kx];
                a0 += w * in[kx + 0];
                a1 += w * in[kx + 1];
                a2 += w * in[kx + 2];
                a3 += w * in[kx + 3];
            }
        }
        int co = cog * 32 + co_l;
        float bias = b1[co];
        float4 o;
        o.x = fmaxf(a0 + bias, 0.f);
        o.y = fmaxf(a1 + bias, 0.f);
        o.z = fmaxf(a2 + bias, 0.f);
        o.w = fmaxf(a3 + bias, 0.f);
        *(float4*)(g_h1 + (long)(b * 256 + co) * 400 + oy * 20 + qx) = o;
    }
}

// ---------------- conv2 via mma.sync bf16 3-term ----------------
// grid (72 ct, 2 mt), 256 threads (8 warps: 2 warp_m x 4 warp_n).
// Block tile: 128co x 128bp. Warp: 64co x 32bp = 4x4 m16n8 tiles, k-chunks of 16.
// B tile (im2col hi/lo bf16) built per ci in dynamic smem, row stride 100 bf16.
#define B_RS 100
#define CONV2_SMEM (128 * B_RS * 2 * 2 + 512)

__global__ void __launch_bounds__(256, 1) conv2_mma(const float* __restrict__ b2) {
    extern __shared__ char smem_raw[];
    __nv_bfloat16* Bhi = (__nv_bfloat16*)smem_raw;                 // [128][B_RS]
    __nv_bfloat16* Blo = Bhi + 128 * B_RS;
    int* koff_s = (int*)(smem_raw + 128 * B_RS * 2 * 2);

    int ct = blockIdx.x;          // 0..71
    int mt = blockIdx.y;          // 0..1
    int tid = threadIdx.x;
    int lane = tid & 31, wid = tid >> 5;
    int warp_m = wid >> 2, warp_n = wid & 3;
    int g = lane >> 2, t = lane & 3;

    // zero both B arrays (covers the k=81..95 pad, written once)
    for (int i = tid; i < 128 * B_RS; i += 256) {
        ((unsigned short*)Bhi)[i] = 0;
        ((unsigned short*)Blo)[i] = 0;
    }
    if (tid < 81) koff_s[tid] = (tid / 9) * 20 + (tid % 9);

    // B-build constants: thread owns one bp column, half of k range
    int bp_l = tid & 127;
    int half = tid >> 7;
    int bp_g = ct * 128 + bp_l;
    int bimg = bp_g / 36;
    int p    = bp_g % 36;
    long ib  = (long)bimg * 102400 + (p / 6) * 40 + (p % 6) * 2;
    int kstart = half * 41;
    int kend   = half ? 81 : 41;

    float C[4][4][4];
    #pragma unroll
    for (int mi = 0; mi < 4; ++mi)
        #pragma unroll
        for (int ni = 0; ni < 4; ++ni)
            #pragma unroll
            for (int e = 0; e < 4; ++e) C[mi][ni][e] = 0.f;

    __syncthreads();

    for (int ci = 0; ci < 256; ++ci) {
        // ---- build B tile for this ci (hi/lo bf16 split) ----
        const float* src = g_h1 + ib + (long)ci * 400;
        for (int k = kstart; k < kend; ++k) {
            float v = src[koff_s[k]];
            __nv_bfloat16 h = __float2bfloat16(v);
            float r = v - __bfloat162float(h);
            Bhi[bp_l * B_RS + k] = h;
            Blo[bp_l * B_RS + k] = __float2bfloat16(r);
        }
        __syncthreads();

        const uint4* Abase = g_w2f + (long)(ci * 2 + mt) * 3072;   // 6*8*2*32

        uint4 Ah[4], Al[4];
        #pragma unroll
        for (int mi = 0; mi < 4; ++mi) {
            int mg = warp_m * 4 + mi;
            Ah[mi] = Abase[(mg * 2 + 0) * 32 + lane];              // chunk 0, s=0
            Al[mi] = Abase[(mg * 2 + 1) * 32 + lane];              // chunk 0, s=1
        }

        #pragma unroll
        for (int c = 0; c < 6; ++c) {
            unsigned bh0[4], bh1[4], bl0[4], bl1[4];
            #pragma unroll
            for (int ni = 0; ni < 4; ++ni) {
                int n  = warp_n * 32 + ni * 8 + g;
                int kb = c * 16 + 2 * t;
                bh0[ni] = *(const unsigned*)(Bhi + n * B_RS + kb);
                bh1[ni] = *(const unsigned*)(Bhi + n * B_RS + kb + 8);
                bl0[ni] = *(const unsigned*)(Blo + n * B_RS + kb);
                bl1[ni] = *(const unsigned*)(Blo + n * B_RS + kb + 8);
            }
            uint4 Ahn[4], Aln[4];
            if (c < 5) {
                #pragma unroll
                for (int mi = 0; mi < 4; ++mi) {
                    int mg = warp_m * 4 + mi;
                    Ahn[mi] = Abase[(((c + 1) * 8 + mg) * 2 + 0) * 32 + lane];
                    Aln[mi] = Abase[(((c + 1) * 8 + mg) * 2 + 1) * 32 + lane];
                }
            }
            #pragma unroll
            for (int mi = 0; mi < 4; ++mi)
                #pragma unroll
                for (int ni = 0; ni < 4; ++ni) {
                    MMA_BF16(C[mi][ni], Ah[mi], bh0[ni], bh1[ni]);  // hi*hi
                    MMA_BF16(C[mi][ni], Ah[mi], bl0[ni], bl1[ni]);  // hi*lo
                    MMA_BF16(C[mi][ni], Al[mi], bh0[ni], bh1[ni]);  // lo*hi
                }
            if (c < 5) {
                #pragma unroll
                for (int mi = 0; mi < 4; ++mi) { Ah[mi] = Ahn[mi]; Al[mi] = Aln[mi]; }
            }
        }
        __syncthreads();
    }

    // ---- epilogue: bias + scatter to g_X[(co*36+p)*256 + b] ----
    #pragma unroll
    for (int mi = 0; mi < 4; ++mi) {
        int r0 = mt * 128 + warp_m * 64 + mi * 16 + g;
        int r1 = r0 + 8;
        float bias0 = b2[r0];
        float bias1 = b2[r1];
        #pragma unroll
        for (int ni = 0; ni < 4; ++ni) {
            int n0 = ct * 128 + warp_n * 32 + ni * 8 + 2 * t;
            int n1 = n0 + 1;
            int b0i = n0 / 36, p0 = n0 % 36;
            int b1i = n1 / 36, p1 = n1 % 36;
            g_X[(long)(r0 * 36 + p0) * 256 + b0i] = C[mi][ni][0] + bias0;
            g_X[(long)(r0 * 36 + p1) * 256 + b1i] = C[mi][ni][1] + bias0;
            g_X[(long)(r1 * 36 + p0) * 256 + b0i] = C[mi][ni][2] + bias1;
            g_X[(long)(r1 * 36 + p1) * 256 + b1i] = C[mi][ni][3] + bias1;
        }
    }
}

// ---------------- primary squash (unchanged) ----------------
__global__ void squash_primary_kernel() {
    int n = blockIdx.x;
    int b = threadIdx.x;
    float v[8];
    float sq = 0.f;
    #pragma unroll
    for (int j = 0; j < 8; ++j) {
        v[j] = g_X[(long)(n * 8 + j) * 256 + b];
        sq += v[j] * v[j];
    }
    float sc = sq / (1.f + sq);
    #pragma unroll
    for (int j = 0; j < 8; ++j) g_X[(long)(n * 8 + j) * 256 + b] = v[j] * sc;
}

// ---------------- u_hat (unchanged) ----------------
__global__ void uhat_kernel(const float* __restrict__ W) {
    int cn = blockIdx.x;
    int n = cn % 1152;
    int b = threadIdx.x;
    __shared__ float w_s[128];
    if (threadIdx.x < 128) w_s[threadIdx.x] = W[(long)cn * 128 + threadIdx.x];
    __syncthreads();
    float xv[8];
    #pragma unroll
    for (int j = 0; j < 8; ++j) xv[j] = g_X[(long)(n * 8 + j) * 256 + b];
    #pragma unroll
    for (int i = 0; i < 16; ++i) {
        float a = 0.f;
        #pragma unroll
        for (int j = 0; j < 8; ++j) a += w_s[i * 8 + j] * xv[j];
        g_uhat[((long)cn * 16 + i) * 256 + b] = a;
    }
}

__global__ void zero_blog() {
    int i = blockIdx.x * 256 + threadIdx.x;
    if (i < CI_ROWS * NCAPS) g_blog[i] = 0.f;
}

// ---------------- routing softmax (unchanged) ----------------
__global__ void probs_kernel() {
    int ci = blockIdx.x;
    const float* row = g_blog + ci * 1152;
    __shared__ float red[256];
    int t = threadIdx.x;
    float m = -1e30f;
    for (int n = t; n < 1152; n += 256) m = fmaxf(m, row[n]);
    red[t] = m; __syncthreads();
    for (int s = 128; s > 0; s >>= 1) { if (t < s) red[t] = fmaxf(red[t], red[t + s]); __syncthreads(); }
    float mx = red[0]; __syncthreads();
    float sum = 0.f;
    for (int n = t; n < 1152; n += 256) sum += expf(row[n] - mx);
    red[t] = sum; __syncthreads();
    for (int s = 128; s > 0; s >>= 1) { if (t < s) red[t] += red[t + s]; __syncthreads(); }
    float tot = red[0];
    for (int n = t; n < 1152; n += 256) g_probs[ci * 1152 + n] = expf(row[n] - mx) / tot;
}

// ---------------- s + squash over batch (unchanged) ----------------
__global__ void s_squash_kernel(int uniform) {
    int ci = blockIdx.x;
    int c = ci >> 4, i = ci & 15;
    int b = threadIdx.x;
    __shared__ float p_s[1152];
    if (!uniform) {
        for (int n = threadIdx.x; n < 1152; n += 256) p_s[n] = g_probs[ci * 1152 + n];
        __syncthreads();
    }
    const float* uh = g_uhat + ((long)(c * 1152) * 16 + i) * 256 + b;
    float acc = 0.f;
    if (uniform) {
        #pragma unroll 8
        for (int n = 0; n < 1152; ++n) acc += uh[(long)n * 4096];
        acc *= (1.0f / 1152.0f);
    } else {
        #pragma unroll 8
        for (int n = 0; n < 1152; ++n) acc += p_s[n] * uh[(long)n * 4096];
    }
    __shared__ float red[256];
    red[b] = acc * acc; __syncthreads();
    for (int s = 128; s > 0; s >>= 1) { if (b < s) red[b] += red[b + s]; __syncthreads(); }
    float sq = red[0];
    float sc = sq / ((1.f + sq) * sqrtf(sq));
    g_outputs[ci * 256 + b] = acc * sc;
}

// ---------------- delta_b (unchanged) ----------------
__global__ void delta_kernel() {
    int ci = blockIdx.x;
    int chunk = blockIdx.y;
    int c = ci >> 4, i = ci & 15;
    int t = threadIdx.x, w = t >> 5, lane = t & 31;
    __shared__ float out_s[256];
    out_s[t] = g_outputs[ci * 256 + t];
    __syncthreads();
    const float* uh = g_uhat + ((long)(c * 1152) * 16 + i) * 256;
    for (int nn = 0; nn < 18; ++nn) {
        int n = chunk * 144 + w * 18 + nn;
        const float* up = uh + (long)n * 4096;
        float v = 0.f;
        #pragma unroll
        for (int k = 0; k < 8; ++k) { int bb = lane + 32 * k; v += up[bb] * out_s[bb]; }
        #pragma unroll
        for (int o = 16; o > 0; o >>= 1) v += __shfl_down_sync(0xffffffffu, v, o);
        if (lane == 0) g_blog[ci * 1152 + n] += v;
    }
}

// ---------------- final (unchanged) ----------------
__global__ void final_kernel(float* __restrict__ out) {
    int cblk = blockIdx.x;
    int b = threadIdx.x;
    float s = 0.f;
    #pragma unroll
    for (int i = 0; i < 16; ++i) {
        float v = g_outputs[(cblk * 16 + i) * 256 + b];
        s += v * v;
    }
    out[b * 10 + cblk] = s;
}

// ---------------- launch ----------------
extern "C" void kernel_launch(void* const* d_in, const int* in_sizes, int n_in,
                              void* d_out, int out_size) {
    const float* x  = (const float*)d_in[0];
    const float* w1 = (const float*)d_in[1];
    const float* b1 = (const float*)d_in[2];
    const float* w2 = (const float*)d_in[3];
    const float* b2 = (const float*)d_in[4];
    const float* W  = (const float*)d_in[5];

    cudaFuncSetAttribute(conv2_mma, cudaFuncAttributeMaxDynamicSharedMemorySize, CONV2_SMEM);

    prepack_w2<<<12288, 256>>>(w2);
    conv1_kernel<<<dim3(8, 256), 256>>>(x, w1, b1);
    conv2_mma<<<dim3(72, 2), 256, CONV2_SMEM>>>(b2);
    squash_primary_kernel<<<1152, 256>>>();
    uhat_kernel<<<11520, 256>>>(W);
    zero_blog<<<720, 256>>>();
    for (int it = 0; it < 3; ++it) {
        if (it > 0) probs_kernel<<<160, 256>>>();
        s_squash_kernel<<<160, 256>>>(it == 0 ? 1 : 0);
        if (it < 2) delta_kernel<<<dim3(160, 8), 256>>>();
    }
    final_kernel<<<10, 256>>>((float*)d_out);
}